// round 17
// baseline (speedup 1.0000x reference)
#include <cuda_runtime.h>
#include <cuda_fp16.h>
#include <cstdint>
#include <math.h>

// B=4, C=128, H=W=256
#define HW    65536
#define CHW   8388608ull
#define CHW2  4194304ull        // half2 elements per image (64 pair-rows x 65536 px)
#define MPAD  264               // B row stride (half2 units)

// ---------------- device scratch ----------------
__device__ float   g_sum[16];
__device__ float   g_inv[21];
__device__ __align__(16) __half2 g_wt[5 * 8 * 1024];   // 1x1 weights, fragment-major
__device__ __align__(16) __half2 g_wmt[288 * 1024];    // mix weights
__device__ __align__(16) __half2 g_xr[4 * CHW2];       // fp16(x), pair layout
__device__ __align__(16) __half2 g_s[12 * CHW2];       // branch outputs
__device__ __align__(16) __half2 g_mid[4 * CHW2];      // mix output

static __device__ __forceinline__ uint32_t smem_u32(const void* p) {
    uint32_t a;
    asm("{ .reg .u64 t; cvta.to.shared.u64 t, %1; cvt.u32.u64 %0, t; }" : "=r"(a) : "l"(p));
    return a;
}
// SiLU via tanh.approx: 1 MUFU
static __device__ __forceinline__ float silu_f(float y) {
    float t;
    asm("tanh.approx.f32 %0, %1;" : "=f"(t) : "f"(y * 0.5f));
    return y * fmaf(0.5f, t, 0.5f);
}
static __device__ __forceinline__ uint32_t relu2(uint32_t v) {
    __half2 z = __float2half2_rn(0.f);
    __half2 r = __hmax2(*(__half2*)&v, z);
    return *(uint32_t*)&r;
}
static __device__ __forceinline__ void mma16(float d[4], uint32_t a0, uint32_t a1,
                                             uint32_t a2, uint32_t a3,
                                             uint32_t b0, uint32_t b1) {
    asm volatile(
        "mma.sync.aligned.m16n8k16.row.col.f32.f16.f16.f32 "
        "{%0,%1,%2,%3}, {%4,%5,%6,%7}, {%8,%9}, {%0,%1,%2,%3};"
        : "+f"(d[0]), "+f"(d[1]), "+f"(d[2]), "+f"(d[3])
        : "r"(a0), "r"(a1), "r"(a2), "r"(a3), "r"(b0), "r"(b1));
}
static __device__ __forceinline__ void cp16(uint32_t dst, const void* src) {
    asm volatile("cp.async.ca.shared.global [%0], [%1], 16;" :: "r"(dst), "l"(src));
}
static __device__ __forceinline__ void cp16z(uint32_t dst, const void* src, bool ok) {
    int sz = ok ? 16 : 0;
    asm volatile("cp.async.ca.shared.global [%0], [%1], 16, %2;" :: "r"(dst), "l"(src), "r"(sz));
}
static __device__ __forceinline__ void cp_commit() {
    asm volatile("cp.async.commit_group;");
}
template <int N> static __device__ __forceinline__ void cp_wait() {
    asm volatile("cp.async.wait_group %0;" :: "n"(N));
}

// k=16 chunk, 4-wide n (warp n=32). A fragment-major [wm][mi][lane][4 regs].
// RELU applies fp16 relu to B fragments at read time.
template <int STRIDE, int RELU>
static __device__ __forceinline__ void mma_chunk(
    const uint32_t* __restrict__ sAf, const uint32_t* __restrict__ sBu,
    float acc[4][4][4], int wm, int lane, int boff) {
    int kq = lane & 3;
    uint32_t bf[4][2];
#pragma unroll
    for (int ni = 0; ni < 4; ni++) {
        bf[ni][0] = sBu[kq * STRIDE + boff + ni * 8];
        bf[ni][1] = sBu[(kq + 4) * STRIDE + boff + ni * 8];
        if (RELU) { bf[ni][0] = relu2(bf[ni][0]); bf[ni][1] = relu2(bf[ni][1]); }
    }
#pragma unroll
    for (int mi = 0; mi < 4; mi++) {
        uint4 av = *(const uint4*)(sAf + (((wm * 4 + mi) * 32 + lane) << 2));
#pragma unroll
        for (int ni = 0; ni < 4; ni++)
            mma16(acc[mi][ni], av.x, av.y, av.z, av.w, bf[ni][0], bf[ni][1]);
    }
}

// mix chunk: all-3-kw B fragments up front, A LDS.128 interleaved with MMA batches.
template <int STRIDE>
static __device__ __forceinline__ void mma_mix3(
    const uint32_t* __restrict__ sA0, const uint32_t* __restrict__ sA1,
    const uint32_t* __restrict__ sA2, const uint32_t* __restrict__ sBu,
    float acc[4][8][4], int wm, int lane, int nbase) {
    int kq = lane & 3;
    uint32_t bf[3][8][2];
#pragma unroll
    for (int kw = 0; kw < 3; kw++)
#pragma unroll
        for (int ni = 0; ni < 8; ni++) {
            int c = 3 + kw + nbase + ni * 8;
            bf[kw][ni][0] = sBu[kq * STRIDE + c];
            bf[kw][ni][1] = sBu[(kq + 4) * STRIDE + c];
        }
#pragma unroll
    for (int mi = 0; mi < 4; mi++) {
        uint32_t aidx = (((wm * 4 + mi) * 32 + lane) << 2);
        uint4 a0 = *(const uint4*)(sA0 + aidx);
#pragma unroll
        for (int ni = 0; ni < 8; ni++)
            mma16(acc[mi][ni], a0.x, a0.y, a0.z, a0.w, bf[0][ni][0], bf[0][ni][1]);
        uint4 a1 = *(const uint4*)(sA1 + aidx);
#pragma unroll
        for (int ni = 0; ni < 8; ni++)
            mma16(acc[mi][ni], a1.x, a1.y, a1.z, a1.w, bf[1][ni][0], bf[1][ni][1]);
        uint4 a2 = *(const uint4*)(sA2 + aidx);
#pragma unroll
        for (int ni = 0; ni < 8; ni++)
            mma16(acc[mi][ni], a2.x, a2.y, a2.z, a2.w, bf[2][ni][0], bf[2][ni][1]);
    }
}

// ---------------- weight prep ----------------
__global__ void prep_weights(const float* __restrict__ w1, const float* __restrict__ w2,
                             const float* __restrict__ w3, const float* __restrict__ wa,
                             const float* __restrict__ wb, const float* __restrict__ wm) {
    int i = blockIdx.x * blockDim.x + threadIdx.x;
    if (i < 16) g_sum[i] = 0.f;
    {
        int inner = i & 1023;
        int ridx = inner & 3, lane = (inner >> 2) & 31, mi = (inner >> 7) & 3;
        int wmn = (inner >> 9) & 1;
        int co = wmn * 64 + mi * 16 + (lane >> 2) + (ridx & 1) * 8;
        int p = (lane & 3) + ((ridx >> 1) & 1) * 4;
        if (i < 40960) {
            int chunk = i >> 10;
            int ck = chunk & 7, s = chunk >> 3;
            const float* w = (s == 0) ? w1 : (s == 1) ? w2 : (s == 2) ? w3
                            : (s == 3) ? wa : wb;
            int ci0 = ck * 16 + p;
            g_wt[i] = __floats2half2_rn(w[co * 128 + ci0], w[co * 128 + ci0 + 8]);
        }
        if (i < 294912) {
            int tile = i >> 10;
            int ck = tile & 7, gg = (tile >> 3) & 3, khw = tile >> 5;
            int kh = khw / 3, kw = khw % 3;
            int ci0 = gg * 128 + ck * 16 + p;
            g_wmt[i] = __floats2half2_rn(wm[((co * 512 + ci0) * 3 + kh) * 3 + kw],
                                         wm[((co * 512 + ci0 + 8) * 3 + kh) * 3 + kw]);
        }
    }
}

// ------- block sums + fp16 pair-layout copy (single stream now) -------
__global__ void block_sums(const float* __restrict__ x) {
    int idx = blockIdx.x;
    int bi = idx & 3, p = (idx >> 2) & 63, b = idx >> 8;
    int c0 = (p >> 3) * 16 + (p & 7);
    int t = threadIdx.x;
    const float* s0 = x + (size_t)b * CHW + (size_t)c0 * HW + (size_t)bi * 16384;
    const float* s1 = s0 + 8 * HW;
    __half2* d_xr = g_xr + (size_t)b * CHW2 + (size_t)p * HW + (size_t)bi * 16384;
    float s = 0.f;
#pragma unroll 4
    for (int h = 0; h < 64; ++h) {
        int off = h * 256 + t;
        float v0 = s0[off], v1 = s1[off];
        s += fmaxf(v0, 0.f) + fmaxf(v1, 0.f);
        d_xr[off] = __floats2half2_rn(v0, v1);
    }
#pragma unroll
    for (int o = 16; o; o >>= 1) s += __shfl_down_sync(0xffffffffu, s, o);
    __shared__ float sm[8];
    if ((t & 31) == 0) sm[t >> 5] = s;
    __syncthreads();
    if (t < 4) atomicAdd(&g_sum[bi * 4 + t], sm[2 * t] + sm[2 * t + 1]);
}

__global__ void compute_inv() {
    if (threadIdx.x == 0 && blockIdx.x == 0) {
        const float cnt4 = 4.f * 128.f * 64.f * 64.f;
        float tot = 0.f, s2[4] = {0.f, 0.f, 0.f, 0.f};
        for (int i = 0; i < 16; i++) {
            float v = g_sum[i];
            tot += v;
            int bi = i >> 2, bj = i & 3;
            s2[(bi >> 1) * 2 + (bj >> 1)] += v;
            g_inv[5 + i] = 1.f / (v / cnt4 + 1e-4f);
        }
        for (int q = 0; q < 4; q++) g_inv[1 + q] = 1.f / (s2[q] / (4.f * cnt4) + 1e-4f);
        g_inv[0] = 1.f / (tot / (16.f * cnt4) + 1e-4f);
    }
}

// epilogue pack: rows (co, co+8) x cols (px, px+1) -> one 8B store in pair layout
static __device__ __forceinline__ void store_pair(__half2* base, int pr, int pxo,
                                                  float q0, float q1, float q2, float q3) {
    __half2 ha = __floats2half2_rn(q0, q2);
    __half2 hb = __floats2half2_rn(q1, q3);
    uint2 uv;
    uv.x = *(uint32_t*)&ha;
    uv.y = *(uint32_t*)&hb;
    *(uint2*)(base + (size_t)pr * HW + pxo) = uv;
}

// ================= scale branches: 3 GEMMs per CTA, B resident, N=256 =================
// grid (256,1,4), 512 thr (16 warps: 2m x 8n). B = g_xr row (relu at fragment read).
__global__ __launch_bounds__(512, 1) void scale_mma(
    const float* __restrict__ g1, const float* __restrict__ b1,
    const float* __restrict__ g2, const float* __restrict__ b2,
    const float* __restrict__ g3, const float* __restrict__ b3) {
    extern __shared__ char smem[];
    char* smB = smem;                 // 8 chunks x 8448 B
    char* smA = smem + 67584;         // 3 bufs x 4096 B
    int b = blockIdx.z, h = blockIdx.x;
    size_t p0 = (size_t)h * 256;
    const __half2* in = g_xr + (size_t)b * CHW2 + p0;
    int tid = threadIdx.x, wid = tid >> 5, lane = tid & 31;
    int wm = wid & 1, wn = wid >> 1;    // wn 0..7
    int g4 = lane >> 2, kq = lane & 3;
    int boff = wn * 32 + g4;
    uint32_t sAa = smem_u32(smA), sBa = smem_u32(smB);
    float acc[4][4][4];
#pragma unroll
    for (int a = 0; a < 4; a++)
#pragma unroll
        for (int c = 0; c < 4; c++)
#pragma unroll
            for (int d = 0; d < 4; d++) acc[a][c][d] = 0.f;

    // B: all 8 k-chunks (8 per thread)
#pragma unroll
    for (int q = 0; q < 8; q++) {
        int e = tid + q * 512;
        int ck = e >> 9, rem = e & 511, row = rem >> 6, p16 = rem & 63;
        cp16(sBa + ck * 8448 + row * 1056 + p16 * 16,
             in + (size_t)(ck * 8 + row) * HW + p16 * 4);
    }
    cp_commit();

    auto loadA = [&](int idx, int buf) {
        if (tid < 256) {
            const __half2* wsrc = g_wt + ((size_t)idx << 10);
            cp16(sAa + buf * 4096 + tid * 16, wsrc + tid * 4);
        }
        cp_commit();
    };

    loadA(0, 0);
    loadA(1, 1);
#pragma unroll 1
    for (int idx = 0; idx < 24; idx++) {
        if (idx < 23) cp_wait<1>(); else cp_wait<0>();
        __syncthreads();
        if (idx < 22) loadA(idx + 2, (idx + 2) % 3);
        int ck = idx & 7;
        mma_chunk<MPAD, 1>((const uint32_t*)(smA + (idx % 3) * 4096),
                           (const uint32_t*)(smB + ck * 8448), acc, wm, lane, boff);
        if (ck == 7) {
            int s = idx >> 3;
            const float* gam = (s == 0) ? g1 : (s == 1) ? g2 : g3;
            const float* bet = (s == 0) ? b1 : (s == 1) ? b2 : b3;
            __half2* outb = g_s + (size_t)(s * 4 + b) * CHW2 + p0;
#pragma unroll
            for (int mi = 0; mi < 4; mi++) {
                int co = wm * 64 + mi * 16 + g4;
                int pr = (wm * 4 + mi) * 8 + g4;
                float gm0 = gam[co], bt0 = bet[co];
                float gm1 = gam[co + 8], bt1 = bet[co + 8];
#pragma unroll
                for (int ni = 0; ni < 4; ni++) {
                    int pxo = wn * 32 + ni * 8 + 2 * kq;
                    float inv;
                    if (s == 0) inv = g_inv[0];
                    else if (s == 1) inv = g_inv[1 + ((h >> 7) << 1) + (pxo >> 7)];
                    else inv = g_inv[5 + ((h >> 6) << 2) + (pxo >> 6)];
                    store_pair(outb, pr, pxo,
                               silu_f(fmaf(acc[mi][ni][0] * inv, gm0, bt0)),
                               silu_f(fmaf(acc[mi][ni][1] * inv, gm0, bt0)),
                               silu_f(fmaf(acc[mi][ni][2] * inv, gm1, bt1)),
                               silu_f(fmaf(acc[mi][ni][3] * inv, gm1, bt1)));
                    acc[mi][ni][0] = acc[mi][ni][1] = 0.f;
                    acc[mi][ni][2] = acc[mi][ni][3] = 0.f;
                }
            }
        }
    }
}

// ================= mix 3x3 conv (512->128) + SiLU =================
// BN=256, 256 thr (8 warps: 2m x 4n, warp tile m64 x n64), 3-stage pipe, 1 sync/iter.
__global__ __launch_bounds__(256, 1) void mix_mma(
    const float* __restrict__ gm_, const float* __restrict__ bm_) {
    extern __shared__ char smem[];
    char* smA = smem;                  // 3 x 12288 B (3 kw x 4096)
    char* smB = smem + 36864;          // 3 x 8448 B (8 rows x 1056)
    int b = blockIdx.z, h = blockIdx.x;
    int tid = threadIdx.x, wid = tid >> 5, lane = tid & 31;
    int wm = wid & 1, wn = wid >> 1;   // wn 0..3
    int g4 = lane >> 2, kq = lane & 3;
    int nbase = wn * 64 + g4;
    uint32_t sAa = smem_u32(smA), sBa = smem_u32(smB);
    float acc[4][8][4];
#pragma unroll
    for (int a = 0; a < 4; a++)
#pragma unroll
        for (int c = 0; c < 8; c++)
#pragma unroll
            for (int d = 0; d < 4; d++) acc[a][c][d] = 0.f;

    if (tid < 48) {
        int st = tid >> 4, rr = (tid >> 1) & 7, side = tid & 1;
        *(uint32_t*)(smB + st * 8448 + rr * 1056 + (side ? 260 : 3) * 4) = 0u;
    }

    const __half2* srcs[4] = {g_xr + (size_t)b * CHW2, g_s + (size_t)b * CHW2,
                              g_s + (size_t)(4 + b) * CHW2, g_s + (size_t)(8 + b) * CHW2};

    auto load = [&](int g, int kh, int ck, int buf) {
        int hh = h + kh - 1;
        bool hok = ((unsigned)hh < 256u);
        const __half2* srcp = srcs[g] + (size_t)(ck * 8) * HW + (size_t)(hok ? hh : 0) * 256;
#pragma unroll
        for (int q = 0; q < 3; q++) {
            int e = tid + q * 256;
            int kwq = e >> 8, inn = e & 255;
            cp16(sAa + buf * 12288 + kwq * 4096 + inn * 16,
                 g_wmt + (((size_t)((kh * 3 + kwq) * 32 + g * 8 + ck)) << 10) + inn * 4);
        }
#pragma unroll
        for (int q = 0; q < 2; q++) {
            int e = tid + q * 256;
            int rr = e >> 6, p16 = e & 63;
            cp16z(sBa + buf * 8448 + rr * 1056 + 16 + p16 * 16,
                  srcp + (size_t)rr * HW + p16 * 4, hok);
        }
        cp_commit();
    };

    int lg = 0, lkh = 0, lck = 0;
    auto adv = [&]() { if (++lck == 8) { lck = 0; if (++lkh == 3) { lkh = 0; ++lg; } } };
    load(lg, lkh, lck, 0); adv();
    load(lg, lkh, lck, 1); adv();

#pragma unroll 1
    for (int it = 0; it < 96; it++) {
        if (it < 95) cp_wait<1>(); else cp_wait<0>();
        __syncthreads();
        if (it < 94) { load(lg, lkh, lck, (it + 2) % 3); adv(); }
        int buf = it % 3;
        const char* sAb = smA + buf * 12288;
        mma_mix3<MPAD>((const uint32_t*)(sAb),
                       (const uint32_t*)(sAb + 4096),
                       (const uint32_t*)(sAb + 8192),
                       (const uint32_t*)(smB + buf * 8448), acc, wm, lane, nbase);
    }

    __half2* outb = g_mid + (size_t)b * CHW2 + (size_t)h * 256;
#pragma unroll
    for (int mi = 0; mi < 4; mi++) {
        int co = wm * 64 + mi * 16 + g4;
        int pr = (wm * 4 + mi) * 8 + g4;
        float gm0 = gm_[co], bt0 = bm_[co], gm1 = gm_[co + 8], bt1 = bm_[co + 8];
#pragma unroll
        for (int ni = 0; ni < 8; ni++) {
            int pxo = wn * 64 + ni * 8 + 2 * kq;
            store_pair(outb, pr, pxo,
                       silu_f(fmaf(acc[mi][ni][0], gm0, bt0)),
                       silu_f(fmaf(acc[mi][ni][1], gm0, bt0)),
                       silu_f(fmaf(acc[mi][ni][2], gm1, bt1)),
                       silu_f(fmaf(acc[mi][ni][3], gm1, bt1)));
        }
    }
}

// ================= fused reweight MLP: GEMM1(SiLU,GELU) -> smem -> GEMM2(SiLU)*res ===========
// grid (256,1,4), 512 thr (16 warps: 2m x 8n, warp n=32), N=256.
__global__ __launch_bounds__(512, 1) void pw_fused(
    const float* __restrict__ ga, const float* __restrict__ ba,
    const float* __restrict__ gb, const float* __restrict__ bb,
    float* __restrict__ dout) {
    extern __shared__ char smem[];
    char* smA  = smem;                  // 3 x 4096 (wa pipeline)
    char* smB  = smem + 12288;          // 3 x 8448 (g_mid pipeline)
    char* smWB = smem + 37632;          // 8 x 4096 (all wb chunks)
    char* smY  = smem + 70400;          // 64 rows x 264 u32 (GELU output, fp16 pairs)
    int b = blockIdx.z;
    size_t p0 = (size_t)blockIdx.x * 256;
    const __half2* in = g_mid + (size_t)b * CHW2 + p0;
    int tid = threadIdx.x, wid = tid >> 5, lane = tid & 31;
    int wm = wid & 1, wn = wid >> 1;    // wn 0..7
    int g4 = lane >> 2, kq = lane & 3;
    int boff = wn * 32 + g4;
    uint32_t sAa = smem_u32(smA), sBa = smem_u32(smB), sWBa = smem_u32(smWB);
    uint32_t* smYu = (uint32_t*)smY;
    float acc[4][4][4];
#pragma unroll
    for (int a = 0; a < 4; a++)
#pragma unroll
        for (int c = 0; c < 4; c++)
#pragma unroll
            for (int d = 0; d < 4; d++) acc[a][c][d] = 0.f;

#pragma unroll
    for (int q = 0; q < 4; q++) {
        int e = tid + q * 512;
        cp16(sWBa + e * 16, g_wt + ((size_t)(4 * 8) << 10) + e * 4);
    }
    cp_commit();

    auto load = [&](int ck, int buf) {
        if (tid < 256) {
            const __half2* wsrc = g_wt + ((size_t)(3 * 8 + ck) << 10);
            cp16(sAa + buf * 4096 + tid * 16, wsrc + tid * 4);
        }
        int row = tid >> 6, p16 = tid & 63;
        cp16(sBa + buf * 8448 + row * 1056 + p16 * 16,
             in + (size_t)(ck * 8 + row) * HW + p16 * 4);
        cp_commit();
    };

    load(0, 0);
    load(1, 1);
#pragma unroll 1
    for (int ck = 0; ck < 8; ck++) {
        if (ck < 7) cp_wait<1>(); else cp_wait<0>();
        __syncthreads();
        if (ck < 6) load(ck + 2, (ck + 2) % 3);
        int buf = ck % 3;
        mma_chunk<MPAD, 0>((const uint32_t*)(smA + buf * 4096),
                           (const uint32_t*)(smB + buf * 8448), acc, wm, lane, boff);
    }

    // epilogue 1: SiLU -> exact GELU -> fp16 pairs into smem Y
#pragma unroll
    for (int mi = 0; mi < 4; mi++) {
        int co = wm * 64 + mi * 16 + g4;
        int pr = (wm * 4 + mi) * 8 + g4;
        float gm0 = ga[co], bt0 = ba[co], gm1 = ga[co + 8], bt1 = ba[co + 8];
#pragma unroll
        for (int ni = 0; ni < 4; ni++) {
            int pxo = wn * 32 + ni * 8 + 2 * kq;
            float y0 = silu_f(fmaf(acc[mi][ni][0], gm0, bt0));
            float y1 = silu_f(fmaf(acc[mi][ni][1], gm0, bt0));
            float y2 = silu_f(fmaf(acc[mi][ni][2], gm1, bt1));
            float y3 = silu_f(fmaf(acc[mi][ni][3], gm1, bt1));
            float q0 = 0.5f * y0 * (1.f + erff(y0 * 0.70710678118654752f));
            float q1 = 0.5f * y1 * (1.f + erff(y1 * 0.70710678118654752f));
            float q2 = 0.5f * y2 * (1.f + erff(y2 * 0.70710678118654752f));
            float q3 = 0.5f * y3 * (1.f + erff(y3 * 0.70710678118654752f));
            __half2 ha = __floats2half2_rn(q0, q2);
            __half2 hb = __floats2half2_rn(q1, q3);
            uint2 uv;
            uv.x = *(uint32_t*)&ha;
            uv.y = *(uint32_t*)&hb;
            *(uint2*)(smYu + pr * MPAD + pxo) = uv;
            acc[mi][ni][0] = acc[mi][ni][1] = 0.f;
            acc[mi][ni][2] = acc[mi][ni][3] = 0.f;
        }
    }
    __syncthreads();

    // GEMM2: A = wb (smem-resident), B = Y (smem-resident)
#pragma unroll 1
    for (int ck = 0; ck < 8; ck++)
        mma_chunk<MPAD, 0>((const uint32_t*)(smWB + ck * 4096),
                           smYu + ck * 8 * MPAD, acc, wm, lane, boff);

    // epilogue 2: SiLU * residual (fp16 x from g_xr), fp32 out
    const __half2* rp = g_xr + (size_t)b * CHW2 + p0;
    float* out = dout + (size_t)b * CHW + p0;
#pragma unroll
    for (int mi = 0; mi < 4; mi++) {
        int co = wm * 64 + mi * 16 + g4;
        int pr = (wm * 4 + mi) * 8 + g4;
        float gm0 = gb[co], bt0 = bb[co], gm1 = gb[co + 8], bt1 = bb[co + 8];
#pragma unroll
        for (int ni = 0; ni < 4; ni++) {
            int pxo = wn * 32 + ni * 8 + 2 * kq;
            float y0 = silu_f(fmaf(acc[mi][ni][0], gm0, bt0));
            float y1 = silu_f(fmaf(acc[mi][ni][1], gm0, bt0));
            float y2 = silu_f(fmaf(acc[mi][ni][2], gm1, bt1));
            float y3 = silu_f(fmaf(acc[mi][ni][3], gm1, bt1));
            uint2 rv = *(const uint2*)(rp + (size_t)pr * HW + pxo);
            __half2 r02 = *(__half2*)&rv.x;
            __half2 r13 = *(__half2*)&rv.y;
            float2 v0, v1;
            v0.x = y0 * __low2float(r02);  v0.y = y1 * __low2float(r13);
            v1.x = y2 * __high2float(r02); v1.y = y3 * __high2float(r13);
            *(float2*)(out + (size_t)co * HW + pxo) = v0;
            *(float2*)(out + (size_t)(co + 8) * HW + pxo) = v1;
        }
    }
}

// ---------------- launch ----------------
extern "C" void kernel_launch(void* const* d_in, const int* in_sizes, int n_in,
                              void* d_out, int out_size) {
    const float* x  = (const float*)d_in[0];
    const float* w1 = (const float*)d_in[1];
    const float* g1 = (const float*)d_in[2];
    const float* b1 = (const float*)d_in[3];
    const float* w2 = (const float*)d_in[4];
    const float* g2 = (const float*)d_in[5];
    const float* b2 = (const float*)d_in[6];
    const float* w3 = (const float*)d_in[7];
    const float* g3 = (const float*)d_in[8];
    const float* b3 = (const float*)d_in[9];
    const float* wm = (const float*)d_in[10];
    const float* gm = (const float*)d_in[11];
    const float* bm = (const float*)d_in[12];
    const float* wa = (const float*)d_in[13];
    const float* ga = (const float*)d_in[14];
    const float* ba = (const float*)d_in[15];
    const float* wb = (const float*)d_in[16];
    const float* gb = (const float*)d_in[17];
    const float* bb = (const float*)d_in[18];
    float* out = (float*)d_out;

    const int SCALE_SMEM = 67584 + 3 * 4096;             // 79872 B
    const int MIX_SMEM   = 3 * (12288 + 8448);           // 62208 B
    const int PWF_SMEM   = 70400 + 64 * MPAD * 4;        // 137984 B
    static int inited = 0;
    if (!inited) {
        cudaFuncSetAttribute(scale_mma, cudaFuncAttributeMaxDynamicSharedMemorySize, SCALE_SMEM);
        cudaFuncSetAttribute(mix_mma,   cudaFuncAttributeMaxDynamicSharedMemorySize, MIX_SMEM);
        cudaFuncSetAttribute(pw_fused,  cudaFuncAttributeMaxDynamicSharedMemorySize, PWF_SMEM);
        inited = 1;
    }

    prep_weights<<<1152, 256>>>(w1, w2, w3, wa, wb, wm);
    block_sums<<<1024, 256>>>(x);
    compute_inv<<<1, 32>>>();
    scale_mma<<<dim3(256, 1, 4), 512, SCALE_SMEM>>>(g1, b1, g2, b2, g3, b3);
    mix_mma<<<dim3(256, 1, 4), 256, MIX_SMEM>>>(gm, bm);
    pw_fused<<<dim3(256, 1, 4), 512, PWF_SMEM>>>(ga, ba, gb, bb, out);
}